// round 16
// baseline (speedup 1.0000x reference)
#include <cuda_runtime.h>
#include <math.h>

#define NN 100000
#define EE 1600000

#define DEV_INF __int_as_float(0x7f800000)

// ---------------------------------------------------------------------------
// f32x2 packed-FMA helpers (sm_103a FFMA2 — only reachable via PTX)
// ---------------------------------------------------------------------------
__device__ __forceinline__ unsigned long long dup_f32(float w) {
    unsigned long long r;
    asm("mov.b64 %0, {%1, %1};" : "=l"(r) : "f"(w));
    return r;
}
__device__ __forceinline__ void fma_f32x2(unsigned long long& d,
                                          unsigned long long a,
                                          unsigned long long b) {
    asm("fma.rn.f32x2 %0, %1, %2, %0;" : "+l"(d) : "l"(a), "l"(b));
}
__device__ __forceinline__ float2 unpack_f32x2(unsigned long long v) {
    float2 r;
    asm("mov.b64 {%0, %1}, %2;" : "=f"(r.x), "=f"(r.y) : "l"(v));
    return r;
}

// ---------------------------------------------------------------------------
// Device scratch (static allocation — no cudaMalloc allowed)
// ---------------------------------------------------------------------------
#define FGRID 625          // persistent grid for fused kernels (625*5 = 3125 tiles)
#define FTILE 32           // nodes per tile

struct Scratch {
    int    cnt[NN];          // in-degree histogram (by dst)
    int    off[NN + 1];      // CSR offsets
    int    cursor[NN];       // scatter cursors
    int    bsum[64];         // scan block sums
    int    csr_src[EE];      // src node per sorted edge
    float4 csr_ea[EE];       // edge_attr in CSR order
    float  dinv[NN];         // (indeg+1)^-0.5 for GCN
    float  ab[(size_t)NN * 128];   // per-node dst/src transforms
    float  h[(size_t)NN * 64];     // h1, then reused for h2
    float  hg[(size_t)NN * 16];    // h2 @ Wg
    float  scratch[(size_t)FGRID * FTILE * 384]; // per-block cat slots (L2-resident ring)
    // folded weights
    float F1t[64 * 384];    // (Wpost1 @ Wlin1)^T  [col][row]
    float F0t[64 * 96];     // (Wpost0 @ Wlin0)^T  [col][row]
    float Wab1[64 * 128];   // [Wpre1_dst | Wpre1_src]
    float Wab0[16 * 32];    // [Wpre0_dst | Wpre0_src]
    float Wc1[4 * 64];      // We1 @ Wpre1_edge
    float Wc0[4 * 16];      // We0 @ Wpre0_edge
    float bc1[64];          // be1 @ Wpre1_edge + bpre1
    float bc0[16];
    float g1[64];           // bpost1 @ Wlin1 + blin1
    float g0[64];
};
__device__ Scratch g_s;

// ---------------------------------------------------------------------------
// Weight folding + cnt zeroing (merged, once per launch)
// ---------------------------------------------------------------------------
__global__ void fold_zero_kernel(
    const float* __restrict__ We0,   const float* __restrict__ be0,
    const float* __restrict__ Wpre0, const float* __restrict__ bpre0,
    const float* __restrict__ Wpost0,const float* __restrict__ bpost0,
    const float* __restrict__ Wlin0, const float* __restrict__ blin0,
    const float* __restrict__ We1,   const float* __restrict__ be1,
    const float* __restrict__ Wpre1, const float* __restrict__ bpre1,
    const float* __restrict__ Wpost1,const float* __restrict__ bpost1,
    const float* __restrict__ Wlin1, const float* __restrict__ blin1)
{
    int tid = blockIdx.x * blockDim.x + threadIdx.x;
    if (tid < NN) { g_s.cnt[tid] = 0; return; }
    tid -= NN;
    if (tid < 24576) { // F1t[c][r] = sum_j Wpost1[r,j] * Wlin1[j,c]
        int c = tid / 384, r = tid - c * 384;
        float acc = 0.f;
        for (int j = 0; j < 64; j++) acc = fmaf(Wpost1[r * 64 + j], Wlin1[j * 64 + c], acc);
        g_s.F1t[tid] = acc; return;
    }
    tid -= 24576;
    if (tid < 6144) { // F0t[c][r] = sum_j Wpost0[r,j] * Wlin0[j,c]
        int c = tid / 96, r = tid - c * 96;
        float acc = 0.f;
        for (int j = 0; j < 64; j++) acc = fmaf(Wpost0[r * 64 + j], Wlin0[j * 64 + c], acc);
        g_s.F0t[tid] = acc; return;
    }
    tid -= 6144;
    if (tid < 8192) { // Wab1 [64,128]
        int j = tid >> 7, f = tid & 127;
        g_s.Wab1[tid] = (f < 64) ? Wpre1[j * 64 + f] : Wpre1[(64 + j) * 64 + (f - 64)];
        return;
    }
    tid -= 8192;
    if (tid < 512) { // Wab0 [16,32]
        int j = tid >> 5, f = tid & 31;
        g_s.Wab0[tid] = (f < 16) ? Wpre0[j * 16 + f] : Wpre0[(16 + j) * 16 + (f - 16)];
        return;
    }
    tid -= 512;
    if (tid < 256) { // Wc1[k,f]
        int kk = tid >> 6, f = tid & 63;
        float acc = 0.f;
        for (int j = 0; j < 64; j++) acc = fmaf(We1[kk * 64 + j], Wpre1[(128 + j) * 64 + f], acc);
        g_s.Wc1[tid] = acc; return;
    }
    tid -= 256;
    if (tid < 64) { // Wc0[k,f]
        int kk = tid >> 4, f = tid & 15;
        float acc = 0.f;
        for (int j = 0; j < 16; j++) acc = fmaf(We0[kk * 16 + j], Wpre0[(32 + j) * 16 + f], acc);
        g_s.Wc0[tid] = acc; return;
    }
    tid -= 64;
    if (tid < 64) { // bc1
        float acc = bpre1[tid];
        for (int j = 0; j < 64; j++) acc = fmaf(be1[j], Wpre1[(128 + j) * 64 + tid], acc);
        g_s.bc1[tid] = acc; return;
    }
    tid -= 64;
    if (tid < 16) { // bc0
        float acc = bpre0[tid];
        for (int j = 0; j < 16; j++) acc = fmaf(be0[j], Wpre0[(32 + j) * 16 + tid], acc);
        g_s.bc0[tid] = acc; return;
    }
    tid -= 16;
    if (tid < 64) { // g1
        float acc = blin1[tid];
        for (int j = 0; j < 64; j++) acc = fmaf(bpost1[j], Wlin1[j * 64 + tid], acc);
        g_s.g1[tid] = acc; return;
    }
    tid -= 64;
    if (tid < 64) { // g0
        float acc = blin0[tid];
        for (int j = 0; j < 64; j++) acc = fmaf(bpost0[j], Wlin0[j * 64 + tid], acc);
        g_s.g0[tid] = acc; return;
    }
}

// ---------------------------------------------------------------------------
// CSR build: histogram -> 2-level scan -> scatter (with edge_attr payload)
// ---------------------------------------------------------------------------
__global__ void hist_kernel(const int* __restrict__ dst)
{
    int i = blockIdx.x * blockDim.x + threadIdx.x;
    if (i < EE) atomicAdd(&g_s.cnt[dst[i]], 1);
}

__global__ void scan1_kernel()
{
    constexpr int B = 512, IT = 4, CHUNK = B * IT; // 2048
    __shared__ int wsum[16];
    int t = threadIdx.x, b = blockIdx.x;
    int base = b * CHUNK + t * IT;
    int v[IT];
    int loc = 0;
#pragma unroll
    for (int i = 0; i < IT; i++) {
        int idx = base + i;
        v[i] = (idx < NN) ? g_s.cnt[idx] : 0;
        loc += v[i];
    }
    int lane = t & 31, w = t >> 5;
    int inc = loc;
    for (int off = 1; off < 32; off <<= 1) {
        int y = __shfl_up_sync(0xffffffffu, inc, off);
        if (lane >= off) inc += y;
    }
    if (lane == 31) wsum[w] = inc;
    __syncthreads();
    if (w == 0) {
        int s = (lane < 16) ? wsum[lane] : 0;
        for (int off = 1; off < 16; off <<= 1) {
            int y = __shfl_up_sync(0xffffffffu, s, off);
            if (lane >= off) s += y;
        }
        if (lane < 16) wsum[lane] = s; // inclusive
    }
    __syncthreads();
    int woff = (w > 0) ? wsum[w - 1] : 0;
    int excl = woff + inc - loc;
#pragma unroll
    for (int i = 0; i < IT; i++) {
        int idx = base + i;
        if (idx < NN) g_s.off[idx] = excl;
        excl += v[i];
    }
    if (t == B - 1) g_s.bsum[b] = woff + inc;
}

__global__ void scan2_kernel(int nb)
{
    int lane = threadIdx.x & 31;
    int a = (lane < nb) ? g_s.bsum[lane] : 0;
    int b = (lane + 32 < nb) ? g_s.bsum[lane + 32] : 0;
    int ia = a, ib = b;
    for (int off = 1; off < 32; off <<= 1) {
        int y = __shfl_up_sync(0xffffffffu, ia, off);
        if (lane >= off) ia += y;
        int z = __shfl_up_sync(0xffffffffu, ib, off);
        if (lane >= off) ib += z;
    }
    int tot0 = __shfl_sync(0xffffffffu, ia, 31);
    if (lane < nb) g_s.bsum[lane] = ia - a;
    if (lane + 32 < nb) g_s.bsum[lane + 32] = ib - b + tot0;
}

__global__ void scan3_kernel()
{
    int i = blockIdx.x * blockDim.x + threadIdx.x;
    if (i < NN) {
        int off = g_s.off[i] + g_s.bsum[i >> 11];
        g_s.off[i] = off;
        g_s.cursor[i] = off;
        g_s.dinv[i] = rsqrtf((float)(g_s.cnt[i] + 1));
    }
    if (i == 0) g_s.off[NN] = EE;
}

__global__ void scatter_kernel(const int* __restrict__ src, const int* __restrict__ dst,
                               const float* __restrict__ ea)
{
    int i = blockIdx.x * blockDim.x + threadIdx.x;
    if (i < EE) {
        int d = dst[i];
        int p = atomicAdd(&g_s.cursor[d], 1);
        g_s.csr_src[p] = src[i];
        g_s.csr_ea[p] = *reinterpret_cast<const float4*>(&ea[(size_t)i * 4]);
    }
}

// ---------------------------------------------------------------------------
// Register-tiled dense matmul (FFMA2, node-dim pairing) for the small
// per-node transforms. SEL: 0 = x->ab0, 2 = h->ab1, 4 = h->hg.
// ---------------------------------------------------------------------------
template <int FIN, int FOUT, int NPB, int KT, int TM, int TN, int SEL>
__global__ void __launch_bounds__((NPB / TM) * (FOUT / TN))
mm_kernel(const float* __restrict__ Xext, const float* __restrict__ Wext)
{
    constexpr int NTH = (NPB / TM) * (FOUT / TN);
    constexpr int XST = NPB + 4;

    const float* X;
    const float* W;
    float* Y;
    if (SEL == 0)      { X = Xext;  W = g_s.Wab0; Y = g_s.ab; }
    else if (SEL == 2) { X = g_s.h; W = g_s.Wab1; Y = g_s.ab; }
    else               { X = g_s.h; W = Wext;     Y = g_s.hg; }

    __shared__ __align__(16) float Xs[KT * XST];
    __shared__ __align__(16) float Ws[KT * FOUT];

    int tid = threadIdx.x;
    int tn = (tid % (FOUT / TN)) * TN;
    int tm = (tid / (FOUT / TN)) * TM;
    int base = blockIdx.x * NPB;

    unsigned long long acc2[TM / 2][TN];
#pragma unroll
    for (int i = 0; i < TM / 2; i++)
#pragma unroll
        for (int j = 0; j < TN; j++) acc2[i][j] = 0ull;

    constexpr int TILES = FIN / KT;
    for (int kt = 0; kt < TILES; kt++) {
        __syncthreads();
        for (int idx = tid; idx < NPB * KT; idx += NTH) {
            int node = idx / KT, k = idx - node * KT;
            int gn = base + node;
            Xs[k * XST + node] = (gn < NN) ? X[(size_t)gn * FIN + kt * KT + k] : 0.f;
        }
        for (int idx = tid; idx < KT * FOUT; idx += NTH)
            Ws[idx] = W[(size_t)kt * KT * FOUT + idx];
        __syncthreads();
#pragma unroll 4
        for (int k = 0; k < KT; k++) {
            unsigned long long xs2[TM / 2];
#pragma unroll
            for (int q = 0; q < TM / 4; q++) {
                ulonglong2 p = *reinterpret_cast<const ulonglong2*>(&Xs[k * XST + tm + 4 * q]);
                xs2[2 * q] = p.x;
                xs2[2 * q + 1] = p.y;
            }
            float wf[TN];
#pragma unroll
            for (int j = 0; j < TN; j += 4)
                *reinterpret_cast<float4*>(&wf[j]) =
                    *reinterpret_cast<const float4*>(&Ws[k * FOUT + tn + j]);
            unsigned long long wd[TN];
#pragma unroll
            for (int j = 0; j < TN; j++) wd[j] = dup_f32(wf[j]);
#pragma unroll
            for (int i = 0; i < TM / 2; i++)
#pragma unroll
                for (int j = 0; j < TN; j++)
                    fma_f32x2(acc2[i][j], xs2[i], wd[j]);
        }
    }

#pragma unroll
    for (int i = 0; i < TM / 2; i++) {
        float lo[TN], hi[TN];
#pragma unroll
        for (int j = 0; j < TN; j++) {
            float2 uv = unpack_f32x2(acc2[i][j]);
            lo[j] = uv.x;
            hi[j] = uv.y;
        }
        int gn0 = base + tm + 2 * i;
        int gn1 = gn0 + 1;
        if (gn0 < NN) {
#pragma unroll
            for (int j = 0; j < TN; j += 4)
                *reinterpret_cast<float4*>(&Y[(size_t)gn0 * FOUT + tn + j]) =
                    *reinterpret_cast<float4*>(&lo[j]);
        }
        if (gn1 < NN) {
#pragma unroll
            for (int j = 0; j < TN; j += 4)
                *reinterpret_cast<float4*>(&Y[(size_t)gn1 * FOUT + tn + j]) =
                    *reinterpret_cast<float4*>(&hi[j]);
        }
    }
}

// ---------------------------------------------------------------------------
// Fused PNA layer 0: aggregation (warp per node) + post matmul (96 -> 64).
// Persistent grid FGRID, block 128 (4 warps), tile = 32 nodes, 5 tiles/block.
// Cat rows live in a per-block global slot (L2-resident ring), staged to smem
// for the register-tiled FFMA2 GEMM (k-dim pairing, zero dup movs).
// ---------------------------------------------------------------------------
__global__ void __launch_bounds__(128, 4) fused0_kernel(const float* __restrict__ x)
{
    constexpr int NT = 3125, XST = 100, WST = 100;
    __shared__ __align__(16) float Xs[FTILE * XST];  // 12.8 KB
    __shared__ __align__(16) float Ws[64 * WST];     // 25.6 KB
    __shared__ float sW[64], sb[16];
    int t = threadIdx.x, lane = t & 31, w = t >> 5;
    if (t < 64) sW[t] = g_s.Wc0[t];
    if (t < 16) sb[t] = g_s.bc0[t];
    __syncthreads();
    int f = lane & 15, half = lane >> 4;
    float w0 = sW[f], w1 = sW[16 + f], w2 = sW[32 + f], w3 = sW[48 + f], bcv = sb[f];
    float* slot = &g_s.scratch[(size_t)blockIdx.x * (FTILE * 96)];
    int ci = (t & 15) * 4, ni = (t >> 4) * 4;

    for (int tile = blockIdx.x; tile < NT; tile += FGRID) {
        int nbase = tile * FTILE;
        // ---- phase A: aggregation, warp w -> nodes w*8 .. w*8+7 ----
        for (int q = 0; q < 8; q++) {
            int nl = w * 8 + q;
            int node = nbase + nl;
            int start = g_s.off[node], end = g_s.off[node + 1];
            float a = g_s.ab[(size_t)node * 32 + f];
            float sA = 0.f, qA = 0.f, sB = 0.f, qB = 0.f;
            float mxA = -DEV_INF, mnA = DEV_INF, mxB = -DEV_INF, mnB = DEV_INF;
            int i = start + half;
            for (; i + 2 < end; i += 4) {
                int sn0 = __ldcs(&g_s.csr_src[i]);
                int sn1 = __ldcs(&g_s.csr_src[i + 2]);
                float4 e0 = __ldcs(&g_s.csr_ea[i]);
                float4 e1 = __ldcs(&g_s.csr_ea[i + 2]);
                float b0 = g_s.ab[(size_t)sn0 * 32 + 16 + f];
                float b1 = g_s.ab[(size_t)sn1 * 32 + 16 + f];
                float c0 = bcv;
                c0 = fmaf(e0.x, w0, c0); c0 = fmaf(e0.y, w1, c0);
                c0 = fmaf(e0.z, w2, c0); c0 = fmaf(e0.w, w3, c0);
                float c1 = bcv;
                c1 = fmaf(e1.x, w0, c1); c1 = fmaf(e1.y, w1, c1);
                c1 = fmaf(e1.z, w2, c1); c1 = fmaf(e1.w, w3, c1);
                float m0 = a + b0 + c0;
                float m1 = a + b1 + c1;
                sA += m0; qA = fmaf(m0, m0, qA); mxA = fmaxf(mxA, m0); mnA = fminf(mnA, m0);
                sB += m1; qB = fmaf(m1, m1, qB); mxB = fmaxf(mxB, m1); mnB = fminf(mnB, m1);
            }
            if (i < end) {
                int sn = __ldcs(&g_s.csr_src[i]);
                float4 e4 = __ldcs(&g_s.csr_ea[i]);
                float b = g_s.ab[(size_t)sn * 32 + 16 + f];
                float c = bcv;
                c = fmaf(e4.x, w0, c); c = fmaf(e4.y, w1, c);
                c = fmaf(e4.z, w2, c); c = fmaf(e4.w, w3, c);
                float m = a + b + c;
                sA += m; qA = fmaf(m, m, qA); mxA = fmaxf(mxA, m); mnA = fminf(mnA, m);
            }
            float sum = sA + sB;
            float ssq = qA + qB;
            float mx = fmaxf(mxA, mxB);
            float mn = fminf(mnA, mnB);
            sum += __shfl_xor_sync(0xffffffffu, sum, 16);
            ssq += __shfl_xor_sync(0xffffffffu, ssq, 16);
            mx = fmaxf(mx, __shfl_xor_sync(0xffffffffu, mx, 16));
            mn = fminf(mn, __shfl_xor_sync(0xffffffffu, mn, 16));
            int deg = end - start;
            float denom = (float)(deg > 0 ? deg : 1);
            float mean = sum / denom;
            float stdv = sqrtf(fmaxf(ssq / denom - mean * mean, 0.f) + 1e-5f);
            if (deg == 0) { mx = 0.f; mn = 0.f; }
            if (lane < 16) {
                float* row = slot + nl * 96;
                row[f]      = x[(size_t)node * 16 + f];
                row[16 + f] = sum;
                row[32 + f] = mean;
                row[48 + f] = mx;
                row[64 + f] = mn;
                row[80 + f] = stdv;
            }
        }
        // ---- phase B: [32,96] @ F0t^T -> [32,64] ----
        __syncthreads();
        for (int i = t; i < FTILE * 24; i += 128) {
            int node = i / 24, qq = (i % 24) * 4;
            *reinterpret_cast<float4*>(&Xs[node * XST + qq]) =
                *reinterpret_cast<const float4*>(slot + node * 96 + qq);
        }
        for (int i = t; i < 64 * 24; i += 128) {
            int col = i / 24, qq = (i % 24) * 4;
            *reinterpret_cast<float4*>(&Ws[col * WST + qq]) =
                *reinterpret_cast<const float4*>(&g_s.F0t[col * 96 + qq]);
        }
        __syncthreads();
        unsigned long long acc[4][4];
#pragma unroll
        for (int i = 0; i < 4; i++)
#pragma unroll
            for (int j = 0; j < 4; j++) acc[i][j] = 0ull;
#pragma unroll
        for (int kk = 0; kk < 96; kk += 4) {
            ulonglong2 xp[4], wp[4];
#pragma unroll
            for (int i = 0; i < 4; i++)
                xp[i] = *reinterpret_cast<const ulonglong2*>(&Xs[(ni + i) * XST + kk]);
#pragma unroll
            for (int j = 0; j < 4; j++)
                wp[j] = *reinterpret_cast<const ulonglong2*>(&Ws[(ci + j) * WST + kk]);
#pragma unroll
            for (int i = 0; i < 4; i++)
#pragma unroll
                for (int j = 0; j < 4; j++) {
                    fma_f32x2(acc[i][j], xp[i].x, wp[j].x);
                    fma_f32x2(acc[i][j], xp[i].y, wp[j].y);
                }
        }
#pragma unroll
        for (int i = 0; i < 4; i++) {
            int node = nbase + ni + i;
            float o[4];
#pragma unroll
            for (int j = 0; j < 4; j++) {
                float2 uv = unpack_f32x2(acc[i][j]);
                o[j] = fmaxf(uv.x + uv.y + g_s.g0[ci + j], 0.f);
            }
            *reinterpret_cast<float4*>(&g_s.h[(size_t)node * 64 + ci]) =
                *reinterpret_cast<float4*>(o);
        }
    }
}

// ---------------------------------------------------------------------------
// Fused PNA layer 1: aggregation (warp per node, 64 feat) + post matmul
// (384 -> 64). Same persistent structure; k-tiled (KT=64, 6 tiles).
// ---------------------------------------------------------------------------
__global__ void __launch_bounds__(128, 4) fused1_kernel()
{
    constexpr int NT = 3125, XST = 68, WST = 68;
    __shared__ __align__(16) float Xs[FTILE * XST];  // 8.7 KB
    __shared__ __align__(16) float Ws[64 * WST];     // 17.4 KB
    __shared__ float sW[256], sb[64];
    int t = threadIdx.x, lane = t & 31, w = t >> 5;
    for (int i = t; i < 256; i += 128) sW[i] = g_s.Wc1[i];
    if (t < 64) sb[t] = g_s.bc1[t];
    __syncthreads();
    float w00 = sW[lane], w01 = sW[64 + lane], w02 = sW[128 + lane], w03 = sW[192 + lane];
    float w10 = sW[32 + lane], w11 = sW[96 + lane], w12 = sW[160 + lane], w13 = sW[224 + lane];
    float bc0 = sb[lane], bc1 = sb[32 + lane];
    float* slot = &g_s.scratch[(size_t)blockIdx.x * (FTILE * 384)];
    int ci = (t & 15) * 4, ni = (t >> 4) * 4;

    for (int tile = blockIdx.x; tile < NT; tile += FGRID) {
        int nbase = tile * FTILE;
        // ---- phase A: aggregation, warp w -> nodes w*8 .. w*8+7 ----
        for (int q = 0; q < 8; q++) {
            int nl = w * 8 + q;
            int node = nbase + nl;
            const float* abn = &g_s.ab[(size_t)node * 128];
            float a0 = abn[lane], a1 = abn[lane + 32];
            int start = g_s.off[node], end = g_s.off[node + 1];
            float s0A = 0.f, q0A = 0.f, s1A = 0.f, q1A = 0.f;
            float s0B = 0.f, q0B = 0.f, s1B = 0.f, q1B = 0.f;
            float mx0A = -DEV_INF, mn0A = DEV_INF, mx1A = -DEV_INF, mn1A = DEV_INF;
            float mx0B = -DEV_INF, mn0B = DEV_INF, mx1B = -DEV_INF, mn1B = DEV_INF;
            int i = start;
            for (; i + 2 <= end; i += 2) {
                int sn0 = __ldcs(&g_s.csr_src[i]);
                int sn1 = __ldcs(&g_s.csr_src[i + 1]);
                float4 e0 = __ldcs(&g_s.csr_ea[i]);
                float4 e1 = __ldcs(&g_s.csr_ea[i + 1]);
                const float* bp0 = &g_s.ab[(size_t)sn0 * 128 + 64];
                const float* bp1 = &g_s.ab[(size_t)sn1 * 128 + 64];
                float b00 = bp0[lane], b01 = bp0[lane + 32];
                float b10 = bp1[lane], b11 = bp1[lane + 32];
                float c;
                c = bc0; c = fmaf(e0.x, w00, c); c = fmaf(e0.y, w01, c);
                c = fmaf(e0.z, w02, c); c = fmaf(e0.w, w03, c);
                float m00 = a0 + b00 + c;
                c = bc1; c = fmaf(e0.x, w10, c); c = fmaf(e0.y, w11, c);
                c = fmaf(e0.z, w12, c); c = fmaf(e0.w, w13, c);
                float m01 = a1 + b01 + c;
                c = bc0; c = fmaf(e1.x, w00, c); c = fmaf(e1.y, w01, c);
                c = fmaf(e1.z, w02, c); c = fmaf(e1.w, w03, c);
                float m10 = a0 + b10 + c;
                c = bc1; c = fmaf(e1.x, w10, c); c = fmaf(e1.y, w11, c);
                c = fmaf(e1.z, w12, c); c = fmaf(e1.w, w13, c);
                float m11 = a1 + b11 + c;
                s0A += m00; q0A = fmaf(m00, m00, q0A); mx0A = fmaxf(mx0A, m00); mn0A = fminf(mn0A, m00);
                s1A += m01; q1A = fmaf(m01, m01, q1A); mx1A = fmaxf(mx1A, m01); mn1A = fminf(mn1A, m01);
                s0B += m10; q0B = fmaf(m10, m10, q0B); mx0B = fmaxf(mx0B, m10); mn0B = fminf(mn0B, m10);
                s1B += m11; q1B = fmaf(m11, m11, q1B); mx1B = fmaxf(mx1B, m11); mn1B = fminf(mn1B, m11);
            }
            if (i < end) {
                int sn = __ldcs(&g_s.csr_src[i]);
                float4 e0 = __ldcs(&g_s.csr_ea[i]);
                const float* bp = &g_s.ab[(size_t)sn * 128 + 64];
                float b0 = bp[lane], b1 = bp[lane + 32];
                float c;
                c = bc0; c = fmaf(e0.x, w00, c); c = fmaf(e0.y, w01, c);
                c = fmaf(e0.z, w02, c); c = fmaf(e0.w, w03, c);
                float m0 = a0 + b0 + c;
                c = bc1; c = fmaf(e0.x, w10, c); c = fmaf(e0.y, w11, c);
                c = fmaf(e0.z, w12, c); c = fmaf(e0.w, w13, c);
                float m1 = a1 + b1 + c;
                s0A += m0; q0A = fmaf(m0, m0, q0A); mx0A = fmaxf(mx0A, m0); mn0A = fminf(mn0A, m0);
                s1A += m1; q1A = fmaf(m1, m1, q1A); mx1A = fmaxf(mx1A, m1); mn1A = fminf(mn1A, m1);
            }
            float s0 = s0A + s0B, q0 = q0A + q0B, s1 = s1A + s1B, q1 = q1A + q1B;
            float mx0 = fmaxf(mx0A, mx0B), mn0 = fminf(mn0A, mn0B);
            float mx1 = fmaxf(mx1A, mx1B), mn1 = fminf(mn1A, mn1B);
            int deg = end - start;
            float denom = (float)(deg > 0 ? deg : 1);
            float mean0 = s0 / denom, mean1 = s1 / denom;
            float std0 = sqrtf(fmaxf(q0 / denom - mean0 * mean0, 0.f) + 1e-5f);
            float std1 = sqrtf(fmaxf(q1 / denom - mean1 * mean1, 0.f) + 1e-5f);
            if (deg == 0) { mx0 = mn0 = 0.f; mx1 = mn1 = 0.f; }
            float* row = slot + nl * 384;
            const float* hrow = &g_s.h[(size_t)node * 64];
            row[lane] = hrow[lane];
            row[lane + 32] = hrow[lane + 32];
            row[64 + lane] = s0;     row[96 + lane] = s1;
            row[128 + lane] = mean0; row[160 + lane] = mean1;
            row[192 + lane] = mx0;   row[224 + lane] = mx1;
            row[256 + lane] = mn0;   row[288 + lane] = mn1;
            row[320 + lane] = std0;  row[352 + lane] = std1;
        }
        // ---- phase B: [32,384] @ F1t^T -> [32,64], k-tiled ----
        unsigned long long acc[4][4];
#pragma unroll
        for (int i = 0; i < 4; i++)
#pragma unroll
            for (int j = 0; j < 4; j++) acc[i][j] = 0ull;
        for (int kt = 0; kt < 6; kt++) {
            __syncthreads();
            for (int i = t; i < FTILE * 16; i += 128) {
                int node = i >> 4, qq = (i & 15) << 2;
                *reinterpret_cast<float4*>(&Xs[node * XST + qq]) =
                    *reinterpret_cast<const float4*>(slot + node * 384 + kt * 64 + qq);
            }
            for (int i = t; i < 64 * 16; i += 128) {
                int col = i >> 4, qq = (i & 15) << 2;
                *reinterpret_cast<float4*>(&Ws[col * WST + qq]) =
                    *reinterpret_cast<const float4*>(&g_s.F1t[col * 384 + kt * 64 + qq]);
            }
            __syncthreads();
#pragma unroll
            for (int kk = 0; kk < 64; kk += 4) {
                ulonglong2 xp[4], wp[4];
#pragma unroll
                for (int i = 0; i < 4; i++)
                    xp[i] = *reinterpret_cast<const ulonglong2*>(&Xs[(ni + i) * XST + kk]);
#pragma unroll
                for (int j = 0; j < 4; j++)
                    wp[j] = *reinterpret_cast<const ulonglong2*>(&Ws[(ci + j) * WST + kk]);
#pragma unroll
                for (int i = 0; i < 4; i++)
#pragma unroll
                    for (int j = 0; j < 4; j++) {
                        fma_f32x2(acc[i][j], xp[i].x, wp[j].x);
                        fma_f32x2(acc[i][j], xp[i].y, wp[j].y);
                    }
            }
        }
#pragma unroll
        for (int i = 0; i < 4; i++) {
            int node = nbase + ni + i;
            float o[4];
#pragma unroll
            for (int j = 0; j < 4; j++) {
                float2 uv = unpack_f32x2(acc[i][j]);
                o[j] = fmaxf(uv.x + uv.y + g_s.g1[ci + j], 0.f);
            }
            *reinterpret_cast<float4*>(&g_s.h[(size_t)node * 64 + ci]) =
                *reinterpret_cast<float4*>(o);
        }
    }
}

// ---------------------------------------------------------------------------
// Fused GCN aggregation + head MLP: warp per node.
// ---------------------------------------------------------------------------
__global__ void gcn_head_kernel(const float* __restrict__ x,
                                const float* __restrict__ bg,
                                const float* __restrict__ Wh1, const float* __restrict__ bh1,
                                const float* __restrict__ Wh2, const float* __restrict__ bh2,
                                float* __restrict__ out)
{
    __shared__ float sW1[320], sW2[100], sb1[16], sb2[16], sbg[16];
    int t = threadIdx.x;
    for (int i = t; i < 320; i += blockDim.x) sW1[i] = Wh1[i];
    for (int i = t; i < 100; i += blockDim.x) sW2[i] = Wh2[i];
    if (t < 10) { sb1[t] = bh1[t]; sb2[t] = bh2[t]; }
    if (t < 16) sbg[t] = bg[t];
    __syncthreads();
    int node = (blockIdx.x * blockDim.x + t) >> 5;
    if (node >= NN) return;
    int lane = t & 31;
    int f = lane & 15, half = lane >> 4;
    int start = g_s.off[node], end = g_s.off[node + 1];
    float accA = 0.f, accB = 0.f;
    int i = start + half;
    for (; i + 2 < end; i += 4) {
        int sn0 = __ldcs(&g_s.csr_src[i]);
        int sn1 = __ldcs(&g_s.csr_src[i + 2]);
        accA = fmaf(g_s.hg[(size_t)sn0 * 16 + f], g_s.dinv[sn0], accA);
        accB = fmaf(g_s.hg[(size_t)sn1 * 16 + f], g_s.dinv[sn1], accB);
    }
    if (i < end) {
        int sn = __ldcs(&g_s.csr_src[i]);
        accA = fmaf(g_s.hg[(size_t)sn * 16 + f], g_s.dinv[sn], accA);
    }
    float acc = accA + accB;
    acc += __shfl_xor_sync(0xffffffffu, acc, 16);
    float dv = g_s.dinv[node];
    float self = g_s.hg[(size_t)node * 16 + f];
    float gval = fmaf(dv * dv, self, dv * acc) + sbg[f];
    float myv = (lane < 16) ? gval : x[(size_t)node * 16 + f];
    int col = (lane < 10) ? lane : 0;
    float z = sb1[col];
#pragma unroll
    for (int j = 0; j < 32; j++) {
        float v = __shfl_sync(0xffffffffu, myv, j);
        z = fmaf(v, sW1[j * 10 + col], z);
    }
    z = fmaxf(z, 0.f);
    float o = sb2[col];
#pragma unroll
    for (int j = 0; j < 10; j++) {
        float v = __shfl_sync(0xffffffffu, z, j);
        o = fmaf(v, sW2[j * 10 + col], o);
    }
    if (lane < 10) out[(size_t)node * 10 + lane] = o;
}

// ---------------------------------------------------------------------------
// Launch
// ---------------------------------------------------------------------------
extern "C" void kernel_launch(void* const* d_in, const int* in_sizes, int n_in,
                              void* d_out, int out_size)
{
    (void)in_sizes; (void)n_in; (void)out_size;
    const float* x      = (const float*)d_in[0];
    const int*   ei     = (const int*)d_in[1];
    const float* ea     = (const float*)d_in[2];
    const float* We0    = (const float*)d_in[3];
    const float* be0    = (const float*)d_in[4];
    const float* Wpre0  = (const float*)d_in[5];
    const float* bpre0  = (const float*)d_in[6];
    const float* Wpost0 = (const float*)d_in[7];
    const float* bpost0 = (const float*)d_in[8];
    const float* Wlin0  = (const float*)d_in[9];
    const float* blin0  = (const float*)d_in[10];
    const float* We1    = (const float*)d_in[11];
    const float* be1    = (const float*)d_in[12];
    const float* Wpre1  = (const float*)d_in[13];
    const float* bpre1  = (const float*)d_in[14];
    const float* Wpost1 = (const float*)d_in[15];
    const float* bpost1 = (const float*)d_in[16];
    const float* Wlin1  = (const float*)d_in[17];
    const float* blin1  = (const float*)d_in[18];
    const float* Wg     = (const float*)d_in[19];
    const float* bg     = (const float*)d_in[20];
    const float* Wh1    = (const float*)d_in[21];
    const float* bh1    = (const float*)d_in[22];
    const float* Wh2    = (const float*)d_in[23];
    const float* bh2    = (const float*)d_in[24];
    float* out = (float*)d_out;

    const int* src = ei;
    const int* dst = ei + EE;

    const int NB_SCAN = (NN + 2047) / 2048; // 49
    const int FOLD_WORK = 24576 + 6144 + 8192 + 512 + 256 + 64 + 64 + 16 + 64 + 64;

    // weight folding + cnt zeroing
    fold_zero_kernel<<<(NN + FOLD_WORK + 255) / 256, 256>>>(
        We0, be0, Wpre0, bpre0, Wpost0, bpost0, Wlin0, blin0,
        We1, be1, Wpre1, bpre1, Wpost1, bpost1, Wlin1, blin1);

    // CSR build (shared by both PNA layers and GCN)
    hist_kernel<<<(EE + 255) / 256, 256>>>(dst);
    scan1_kernel<<<NB_SCAN, 512>>>();
    scan2_kernel<<<1, 32>>>(NB_SCAN);
    scan3_kernel<<<(NN + 255) / 256, 256>>>();
    scatter_kernel<<<(EE + 255) / 256, 256>>>(src, dst, ea);

    // ---- PNA layer 0 ----
    mm_kernel<16, 32, 128, 16, 8, 8, 0><<<(NN + 127) / 128, 64>>>(x, nullptr);   // a0|b0
    fused0_kernel<<<FGRID, 128>>>(x);                                            // agg0 + post0 -> h1

    // ---- PNA layer 1 ----
    mm_kernel<64, 128, 64, 32, 8, 8, 2><<<(NN + 63) / 64, 128>>>(nullptr, nullptr); // a1|b1
    fused1_kernel<<<FGRID, 128>>>();                                             // agg1 + post1 -> h2

    // ---- GCN matmul ----
    mm_kernel<64, 16, 64, 32, 4, 4, 4><<<(NN + 63) / 64, 64>>>(nullptr, Wg);     // hg

    // ---- fused GCN aggregation + head ----
    gcn_head_kernel<<<(NN * 32 + 255) / 256, 256>>>(x, bg, Wh1, bh1, Wh2, bh2, out);
}

// round 17
// speedup vs baseline: 1.9160x; 1.9160x over previous
#include <cuda_runtime.h>
#include <math.h>

#define NN 100000
#define EE 1600000

#define DEV_INF __int_as_float(0x7f800000)

// ---------------------------------------------------------------------------
// f32x2 packed-FMA helpers (sm_103a FFMA2 — only reachable via PTX)
// ---------------------------------------------------------------------------
__device__ __forceinline__ unsigned long long dup_f32(float w) {
    unsigned long long r;
    asm("mov.b64 %0, {%1, %1};" : "=l"(r) : "f"(w));
    return r;
}
__device__ __forceinline__ void fma_f32x2(unsigned long long& d,
                                          unsigned long long a,
                                          unsigned long long b) {
    asm("fma.rn.f32x2 %0, %1, %2, %0;" : "+l"(d) : "l"(a), "l"(b));
}
__device__ __forceinline__ float2 unpack_f32x2(unsigned long long v) {
    float2 r;
    asm("mov.b64 {%0, %1}, %2;" : "=f"(r.x), "=f"(r.y) : "l"(v));
    return r;
}

// ---------------------------------------------------------------------------
// Device scratch (static allocation — no cudaMalloc allowed)
// ---------------------------------------------------------------------------
struct Scratch {
    int    cnt[NN];          // in-degree histogram (by dst)
    int    off[NN + 1];      // CSR offsets
    int    cursor[NN];       // scatter cursors
    int    bsum[64];         // scan block sums
    int    csr_src[EE];      // src node per sorted edge
    float4 csr_ea[EE];       // edge_attr in CSR order
    float  dinv[NN];         // (indeg+1)^-0.5 for GCN
    float  ab[(size_t)NN * 128];   // per-node dst/src transforms
    float  h[(size_t)NN * 64];     // h1, then reused for h2
    float  hg[(size_t)NN * 16];    // h2 @ Wg
    float  cat[(size_t)NN * 384];  // concat rows (layer0 stride 96, layer1 stride 384)
    // folded weights
    float F1[384 * 64];     // Wpost1 @ Wlin1
    float F0[96 * 64];      // Wpost0 @ Wlin0
    float Wab1[64 * 128];   // [Wpre1_dst | Wpre1_src]
    float Wab0[16 * 32];    // [Wpre0_dst | Wpre0_src]
    float Wc1[4 * 64];      // We1 @ Wpre1_edge
    float Wc0[4 * 16];      // We0 @ Wpre0_edge
    float bc1[64];          // be1 @ Wpre1_edge + bpre1
    float bc0[16];
    float g1[64];           // bpost1 @ Wlin1 + blin1
    float g0[64];
};
__device__ Scratch g_s;

// ---------------------------------------------------------------------------
// Weight folding + cnt zeroing (merged, once per launch)
// ---------------------------------------------------------------------------
__global__ void fold_zero_kernel(
    const float* __restrict__ We0,   const float* __restrict__ be0,
    const float* __restrict__ Wpre0, const float* __restrict__ bpre0,
    const float* __restrict__ Wpost0,const float* __restrict__ bpost0,
    const float* __restrict__ Wlin0, const float* __restrict__ blin0,
    const float* __restrict__ We1,   const float* __restrict__ be1,
    const float* __restrict__ Wpre1, const float* __restrict__ bpre1,
    const float* __restrict__ Wpost1,const float* __restrict__ bpost1,
    const float* __restrict__ Wlin1, const float* __restrict__ blin1)
{
    int tid = blockIdx.x * blockDim.x + threadIdx.x;
    if (tid < NN) { g_s.cnt[tid] = 0; return; }
    tid -= NN;
    if (tid < 24576) { // F1 = Wpost1[384,64] @ Wlin1[64,64]
        int r = tid >> 6, c = tid & 63;
        float acc = 0.f;
        for (int j = 0; j < 64; j++) acc = fmaf(Wpost1[r * 64 + j], Wlin1[j * 64 + c], acc);
        g_s.F1[tid] = acc; return;
    }
    tid -= 24576;
    if (tid < 6144) { // F0 = Wpost0[96,64] @ Wlin0[64,64]
        int r = tid >> 6, c = tid & 63;
        float acc = 0.f;
        for (int j = 0; j < 64; j++) acc = fmaf(Wpost0[r * 64 + j], Wlin0[j * 64 + c], acc);
        g_s.F0[tid] = acc; return;
    }
    tid -= 6144;
    if (tid < 8192) { // Wab1 [64,128]
        int j = tid >> 7, f = tid & 127;
        g_s.Wab1[tid] = (f < 64) ? Wpre1[j * 64 + f] : Wpre1[(64 + j) * 64 + (f - 64)];
        return;
    }
    tid -= 8192;
    if (tid < 512) { // Wab0 [16,32]
        int j = tid >> 5, f = tid & 31;
        g_s.Wab0[tid] = (f < 16) ? Wpre0[j * 16 + f] : Wpre0[(16 + j) * 16 + (f - 16)];
        return;
    }
    tid -= 512;
    if (tid < 256) { // Wc1[k,f] = sum_j We1[k,j] * Wpre1[128+j, f]
        int kk = tid >> 6, f = tid & 63;
        float acc = 0.f;
        for (int j = 0; j < 64; j++) acc = fmaf(We1[kk * 64 + j], Wpre1[(128 + j) * 64 + f], acc);
        g_s.Wc1[tid] = acc; return;
    }
    tid -= 256;
    if (tid < 64) { // Wc0[k,f]
        int kk = tid >> 4, f = tid & 15;
        float acc = 0.f;
        for (int j = 0; j < 16; j++) acc = fmaf(We0[kk * 16 + j], Wpre0[(32 + j) * 16 + f], acc);
        g_s.Wc0[tid] = acc; return;
    }
    tid -= 64;
    if (tid < 64) { // bc1
        float acc = bpre1[tid];
        for (int j = 0; j < 64; j++) acc = fmaf(be1[j], Wpre1[(128 + j) * 64 + tid], acc);
        g_s.bc1[tid] = acc; return;
    }
    tid -= 64;
    if (tid < 16) { // bc0
        float acc = bpre0[tid];
        for (int j = 0; j < 16; j++) acc = fmaf(be0[j], Wpre0[(32 + j) * 16 + tid], acc);
        g_s.bc0[tid] = acc; return;
    }
    tid -= 16;
    if (tid < 64) { // g1
        float acc = blin1[tid];
        for (int j = 0; j < 64; j++) acc = fmaf(bpost1[j], Wlin1[j * 64 + tid], acc);
        g_s.g1[tid] = acc; return;
    }
    tid -= 64;
    if (tid < 64) { // g0
        float acc = blin0[tid];
        for (int j = 0; j < 64; j++) acc = fmaf(bpost0[j], Wlin0[j * 64 + tid], acc);
        g_s.g0[tid] = acc; return;
    }
}

// ---------------------------------------------------------------------------
// CSR build: histogram -> scan (block prefix recomputed per block) -> scatter
// ---------------------------------------------------------------------------
__global__ void hist_kernel(const int* __restrict__ dst)
{
    int i = blockIdx.x * blockDim.x + threadIdx.x;
    if (i < EE) atomicAdd(&g_s.cnt[dst[i]], 1);
}

__global__ void scan1_kernel()
{
    constexpr int B = 512, IT = 4, CHUNK = B * IT; // 2048
    __shared__ int wsum[16];
    int t = threadIdx.x, b = blockIdx.x;
    int base = b * CHUNK + t * IT;
    int v[IT];
    int loc = 0;
#pragma unroll
    for (int i = 0; i < IT; i++) {
        int idx = base + i;
        v[i] = (idx < NN) ? g_s.cnt[idx] : 0;
        loc += v[i];
    }
    int lane = t & 31, w = t >> 5;
    int inc = loc;
    for (int off = 1; off < 32; off <<= 1) {
        int y = __shfl_up_sync(0xffffffffu, inc, off);
        if (lane >= off) inc += y;
    }
    if (lane == 31) wsum[w] = inc;
    __syncthreads();
    if (w == 0) {
        int s = (lane < 16) ? wsum[lane] : 0;
        for (int off = 1; off < 16; off <<= 1) {
            int y = __shfl_up_sync(0xffffffffu, s, off);
            if (lane >= off) s += y;
        }
        if (lane < 16) wsum[lane] = s; // inclusive
    }
    __syncthreads();
    int woff = (w > 0) ? wsum[w - 1] : 0;
    int excl = woff + inc - loc;
#pragma unroll
    for (int i = 0; i < IT; i++) {
        int idx = base + i;
        if (idx < NN) g_s.off[idx] = excl;
        excl += v[i];
    }
    if (t == B - 1) g_s.bsum[b] = woff + inc;
}

// scan3 with in-block chunk-prefix (replaces the serial scan2 launch):
// each 256-wide block lies inside one 2048-chunk; warp 0 reduces
// bsum[0..chunk) and broadcasts through smem.
__global__ void scan3_kernel()
{
    __shared__ int spref;
    int b = blockIdx.x, t = threadIdx.x;
    int chunk = (b * 256) >> 11;
    if (t < 32) {
        int v = 0;
        if (t < chunk) v = g_s.bsum[t];
        if (t + 32 < chunk) v += g_s.bsum[t + 32];
#pragma unroll
        for (int off = 16; off; off >>= 1) v += __shfl_xor_sync(0xffffffffu, v, off);
        if (t == 0) spref = v;
    }
    __syncthreads();
    int pref = spref;
    int i = b * 256 + t;
    if (i < NN) {
        int off = g_s.off[i] + pref;
        g_s.off[i] = off;
        g_s.cursor[i] = off;
        g_s.dinv[i] = rsqrtf((float)(g_s.cnt[i] + 1));
    }
    if (i == 0) g_s.off[NN] = EE;
}

__global__ void scatter_kernel(const int* __restrict__ src, const int* __restrict__ dst,
                               const float* __restrict__ ea)
{
    int i = blockIdx.x * blockDim.x + threadIdx.x;
    if (i < EE) {
        int d = dst[i];
        int p = atomicAdd(&g_s.cursor[d], 1);
        g_s.csr_src[p] = src[i];
        g_s.csr_ea[p] = *reinterpret_cast<const float4*>(&ea[(size_t)i * 4]);
    }
}

// ---------------------------------------------------------------------------
// Register-tiled dense matmul with packed f32x2 FMA:
// Y[N,FOUT] = X[N,FIN] @ W (+bias)(relu?). Each thread owns TM nodes x TN
// cols; accumulators packed in pairs along the node dim. Xs stored transposed
// [k][node] (+4 pad); X and W staged with float4 loads. NPB=128 halves the
// per-block weight re-fetch vs NPB=64. SEL picks buffers at compile time.
// ---------------------------------------------------------------------------
template <int FIN, int FOUT, int NPB, int KT, int TM, int TN, bool BIAS, bool RELU, int SEL>
__global__ void __launch_bounds__((NPB / TM) * (FOUT / TN))
mm_kernel(const float* __restrict__ Xext, const float* __restrict__ Wext)
{
    constexpr int NTH = (NPB / TM) * (FOUT / TN);
    constexpr int XST = NPB + 4;
    constexpr int KQ = KT / 4;
    constexpr bool STREAMX = (SEL == 1 || SEL == 3);

    const float* X;
    const float* W;
    const float* bias = nullptr;
    float* Y;
    if (SEL == 0)      { X = Xext;    W = g_s.Wab0;                   Y = g_s.ab; }
    else if (SEL == 1) { X = g_s.cat; W = g_s.F0;   bias = g_s.g0;    Y = g_s.h;  }
    else if (SEL == 2) { X = g_s.h;   W = g_s.Wab1;                   Y = g_s.ab; }
    else if (SEL == 3) { X = g_s.cat; W = g_s.F1;   bias = g_s.g1;    Y = g_s.h;  }
    else               { X = g_s.h;   W = Wext;                       Y = g_s.hg; }

    __shared__ __align__(16) float Xs[KT * XST];
    __shared__ __align__(16) float Ws[KT * FOUT];

    int tid = threadIdx.x;
    int tn = (tid % (FOUT / TN)) * TN;
    int tm = (tid / (FOUT / TN)) * TM;
    int base = blockIdx.x * NPB;

    unsigned long long acc2[TM / 2][TN];
#pragma unroll
    for (int i = 0; i < TM / 2; i++)
#pragma unroll
        for (int j = 0; j < TN; j++) acc2[i][j] = 0ull;

    constexpr int TILES = FIN / KT;
    for (int kt = 0; kt < TILES; kt++) {
        __syncthreads();
        for (int idx = tid; idx < NPB * KQ; idx += NTH) {
            int node = idx / KQ, kq = idx - node * KQ;
            int gn = base + node;
            float4 v = make_float4(0.f, 0.f, 0.f, 0.f);
            if (gn < NN) {
                const float4* p = reinterpret_cast<const float4*>(
                    &X[(size_t)gn * FIN + kt * KT + kq * 4]);
                v = STREAMX ? __ldcs(p) : *p;
            }
            Xs[(kq * 4 + 0) * XST + node] = v.x;
            Xs[(kq * 4 + 1) * XST + node] = v.y;
            Xs[(kq * 4 + 2) * XST + node] = v.z;
            Xs[(kq * 4 + 3) * XST + node] = v.w;
        }
        for (int idx = tid; idx < KT * FOUT / 4; idx += NTH)
            *reinterpret_cast<float4*>(&Ws[idx * 4]) =
                *reinterpret_cast<const float4*>(&W[(size_t)kt * KT * FOUT + idx * 4]);
        __syncthreads();
#pragma unroll 4
        for (int k = 0; k < KT; k++) {
            unsigned long long xs2[TM / 2];
#pragma unroll
            for (int q = 0; q < TM / 4; q++) {
                ulonglong2 p = *reinterpret_cast<const ulonglong2*>(&Xs[k * XST + tm + 4 * q]);
                xs2[2 * q] = p.x;
                xs2[2 * q + 1] = p.y;
            }
            float wf[TN];
#pragma unroll
            for (int j = 0; j < TN; j += 4)
                *reinterpret_cast<float4*>(&wf[j]) =
                    *reinterpret_cast<const float4*>(&Ws[k * FOUT + tn + j]);
            unsigned long long wd[TN];
#pragma unroll
            for (int j = 0; j < TN; j++) wd[j] = dup_f32(wf[j]);
#pragma unroll
            for (int i = 0; i < TM / 2; i++)
#pragma unroll
                for (int j = 0; j < TN; j++)
                    fma_f32x2(acc2[i][j], xs2[i], wd[j]);
        }
    }

    float bv[TN];
#pragma unroll
    for (int j = 0; j < TN; j++) bv[j] = BIAS ? bias[tn + j] : 0.f;
#pragma unroll
    for (int i = 0; i < TM / 2; i++) {
        float lo[TN], hi[TN];
#pragma unroll
        for (int j = 0; j < TN; j++) {
            float2 uv = unpack_f32x2(acc2[i][j]);
            lo[j] = uv.x + bv[j];
            hi[j] = uv.y + bv[j];
            if (RELU) { lo[j] = fmaxf(lo[j], 0.f); hi[j] = fmaxf(hi[j], 0.f); }
        }
        int gn0 = base + tm + 2 * i;
        int gn1 = gn0 + 1;
        if (gn0 < NN) {
#pragma unroll
            for (int j = 0; j < TN; j += 4)
                *reinterpret_cast<float4*>(&Y[(size_t)gn0 * FOUT + tn + j]) =
                    *reinterpret_cast<float4*>(&lo[j]);
        }
        if (gn1 < NN) {
#pragma unroll
            for (int j = 0; j < TN; j += 4)
                *reinterpret_cast<float4*>(&Y[(size_t)gn1 * FOUT + tn + j]) =
                    *reinterpret_cast<float4*>(&hi[j]);
        }
    }
}

// ---------------------------------------------------------------------------
// PNA aggregation, layer 0 (Fin=16): one warp per node, 16 lanes=features,
// 2 edge-halves, unrolled x2 with dual accumulators.
// Writes concat row [x | s | mean | max | min | std] (96).
// ---------------------------------------------------------------------------
__global__ void agg0_kernel(const float* __restrict__ x)
{
    __shared__ float sW[64];
    __shared__ float sb[16];
    int t = threadIdx.x;
    if (t < 64) sW[t] = g_s.Wc0[t];
    if (t < 16) sb[t] = g_s.bc0[t];
    __syncthreads();
    int node = (blockIdx.x * blockDim.x + t) >> 5;
    if (node >= NN) return;
    int lane = t & 31;
    int f = lane & 15, half = lane >> 4;
    float w0 = sW[f], w1 = sW[16 + f], w2 = sW[32 + f], w3 = sW[48 + f], bc = sb[f];
    int start = g_s.off[node], end = g_s.off[node + 1];
    float a = g_s.ab[(size_t)node * 32 + f];
    float sA = 0.f, qA = 0.f, sB = 0.f, qB = 0.f;
    float mxA = -DEV_INF, mnA = DEV_INF, mxB = -DEV_INF, mnB = DEV_INF;
    int i = start + half;
    for (; i + 2 < end; i += 4) {
        int sn0 = __ldcs(&g_s.csr_src[i]);
        int sn1 = __ldcs(&g_s.csr_src[i + 2]);
        float4 e0 = __ldcs(&g_s.csr_ea[i]);
        float4 e1 = __ldcs(&g_s.csr_ea[i + 2]);
        float b0 = g_s.ab[(size_t)sn0 * 32 + 16 + f];
        float b1 = g_s.ab[(size_t)sn1 * 32 + 16 + f];
        float c0 = bc;
        c0 = fmaf(e0.x, w0, c0); c0 = fmaf(e0.y, w1, c0);
        c0 = fmaf(e0.z, w2, c0); c0 = fmaf(e0.w, w3, c0);
        float c1 = bc;
        c1 = fmaf(e1.x, w0, c1); c1 = fmaf(e1.y, w1, c1);
        c1 = fmaf(e1.z, w2, c1); c1 = fmaf(e1.w, w3, c1);
        float m0 = a + b0 + c0;
        float m1 = a + b1 + c1;
        sA += m0; qA = fmaf(m0, m0, qA); mxA = fmaxf(mxA, m0); mnA = fminf(mnA, m0);
        sB += m1; qB = fmaf(m1, m1, qB); mxB = fmaxf(mxB, m1); mnB = fminf(mnB, m1);
    }
    if (i < end) {
        int sn = __ldcs(&g_s.csr_src[i]);
        float4 e4 = __ldcs(&g_s.csr_ea[i]);
        float b = g_s.ab[(size_t)sn * 32 + 16 + f];
        float c = bc;
        c = fmaf(e4.x, w0, c); c = fmaf(e4.y, w1, c);
        c = fmaf(e4.z, w2, c); c = fmaf(e4.w, w3, c);
        float m = a + b + c;
        sA += m; qA = fmaf(m, m, qA); mxA = fmaxf(mxA, m); mnA = fminf(mnA, m);
    }
    float sum = sA + sB;
    float ssq = qA + qB;
    float mx = fmaxf(mxA, mxB);
    float mn = fminf(mnA, mnB);
    sum += __shfl_xor_sync(0xffffffffu, sum, 16);
    ssq += __shfl_xor_sync(0xffffffffu, ssq, 16);
    mx = fmaxf(mx, __shfl_xor_sync(0xffffffffu, mx, 16));
    mn = fminf(mn, __shfl_xor_sync(0xffffffffu, mn, 16));
    int deg = end - start;
    float denom = (float)(deg > 0 ? deg : 1);
    float mean = sum / denom;
    float msq = ssq / denom;
    float stdv = sqrtf(fmaxf(msq - mean * mean, 0.f) + 1e-5f);
    if (deg == 0) { mx = 0.f; mn = 0.f; }
    if (lane < 16) {
        float* row = &g_s.cat[(size_t)node * 96];
        row[f]      = x[(size_t)node * 16 + f];
        row[16 + f] = sum;
        row[32 + f] = mean;
        row[48 + f] = mx;
        row[64 + f] = mn;
        row[80 + f] = stdv;
    }
}

// ---------------------------------------------------------------------------
// PNA aggregation, layer 1 (Fin=64): one warp per node, lane owns features
// (lane, lane+32), unrolled x2 with dual accumulator sets.
// Writes concat row [h1 | s | mean | max | min | std] (384).
// ---------------------------------------------------------------------------
__global__ void agg1_kernel()
{
    __shared__ float sW[256];
    __shared__ float sb[64];
    int t = threadIdx.x;
    if (t < 256) sW[t] = g_s.Wc1[t];
    if (t < 64) sb[t] = g_s.bc1[t];
    __syncthreads();
    int node = (blockIdx.x * blockDim.x + t) >> 5;
    if (node >= NN) return;
    int lane = t & 31;
    float w00 = sW[lane], w01 = sW[64 + lane], w02 = sW[128 + lane], w03 = sW[192 + lane];
    float w10 = sW[32 + lane], w11 = sW[96 + lane], w12 = sW[160 + lane], w13 = sW[224 + lane];
    float bc0 = sb[lane], bc1 = sb[32 + lane];
    const float* abn = &g_s.ab[(size_t)node * 128];
    float a0 = abn[lane], a1 = abn[lane + 32];
    int start = g_s.off[node], end = g_s.off[node + 1];
    float s0A = 0.f, q0A = 0.f, s1A = 0.f, q1A = 0.f;
    float s0B = 0.f, q0B = 0.f, s1B = 0.f, q1B = 0.f;
    float mx0A = -DEV_INF, mn0A = DEV_INF, mx1A = -DEV_INF, mn1A = DEV_INF;
    float mx0B = -DEV_INF, mn0B = DEV_INF, mx1B = -DEV_INF, mn1B = DEV_INF;
    int i = start;
    for (; i + 2 <= end; i += 2) {
        int sn0 = __ldcs(&g_s.csr_src[i]);
        int sn1 = __ldcs(&g_s.csr_src[i + 1]);
        float4 e0 = __ldcs(&g_s.csr_ea[i]);
        float4 e1 = __ldcs(&g_s.csr_ea[i + 1]);
        const float* bp0 = &g_s.ab[(size_t)sn0 * 128 + 64];
        const float* bp1 = &g_s.ab[(size_t)sn1 * 128 + 64];
        float b00 = bp0[lane], b01 = bp0[lane + 32];
        float b10 = bp1[lane], b11 = bp1[lane + 32];
        float c;
        c = bc0; c = fmaf(e0.x, w00, c); c = fmaf(e0.y, w01, c);
        c = fmaf(e0.z, w02, c); c = fmaf(e0.w, w03, c);
        float m00 = a0 + b00 + c;
        c = bc1; c = fmaf(e0.x, w10, c); c = fmaf(e0.y, w11, c);
        c = fmaf(e0.z, w12, c); c = fmaf(e0.w, w13, c);
        float m01 = a1 + b01 + c;
        c = bc0; c = fmaf(e1.x, w00, c); c = fmaf(e1.y, w01, c);
        c = fmaf(e1.z, w02, c); c = fmaf(e1.w, w03, c);
        float m10 = a0 + b10 + c;
        c = bc1; c = fmaf(e1.x, w10, c); c = fmaf(e1.y, w11, c);
        c = fmaf(e1.z, w12, c); c = fmaf(e1.w, w13, c);
        float m11 = a1 + b11 + c;
        s0A += m00; q0A = fmaf(m00, m00, q0A); mx0A = fmaxf(mx0A, m00); mn0A = fminf(mn0A, m00);
        s1A += m01; q1A = fmaf(m01, m01, q1A); mx1A = fmaxf(mx1A, m01); mn1A = fminf(mn1A, m01);
        s0B += m10; q0B = fmaf(m10, m10, q0B); mx0B = fmaxf(mx0B, m10); mn0B = fminf(mn0B, m10);
        s1B += m11; q1B = fmaf(m11, m11, q1B); mx1B = fmaxf(mx1B, m11); mn1B = fminf(mn1B, m11);
    }
    if (i < end) {
        int sn = __ldcs(&g_s.csr_src[i]);
        float4 e0 = __ldcs(&g_s.csr_ea[i]);
        const float* bp = &g_s.ab[(size_t)sn * 128 + 64];
        float b0 = bp[lane], b1 = bp[lane + 32];
        float c;
        c = bc0; c = fmaf(e0.x, w00, c); c = fmaf(e0.y, w01, c);
        c = fmaf(e0.z, w02, c); c = fmaf(e0.w, w03, c);
        float m0 = a0 + b0 + c;
        c = bc1; c = fmaf(e0.x, w10, c); c = fmaf(e0.y, w11, c);
        c = fmaf(e0.z, w12, c); c = fmaf(e0.w, w13, c);
        float m1 = a1 + b1 + c;
        s0A += m0; q0A = fmaf(m0, m0, q0A); mx0A = fmaxf(mx0A, m0); mn0A = fminf(mn0A, m0);
        s1A += m1; q1A = fmaf(m1, m1, q1A); mx1A = fmaxf(mx1A, m1); mn1A = fminf(mn1A, m1);
    }
    float s0 = s0A + s0B, q0 = q0A + q0B, s1 = s1A + s1B, q1 = q1A + q1B;
    float mx0 = fmaxf(mx0A, mx0B), mn0 = fminf(mn0A, mn0B);
    float mx1 = fmaxf(mx1A, mx1B), mn1 = fminf(mn1A, mn1B);
    int deg = end - start;
    float denom = (float)(deg > 0 ? deg : 1);
    float mean0 = s0 / denom, mean1 = s1 / denom;
    float std0 = sqrtf(fmaxf(q0 / denom - mean0 * mean0, 0.f) + 1e-5f);
    float std1 = sqrtf(fmaxf(q1 / denom - mean1 * mean1, 0.f) + 1e-5f);
    if (deg == 0) { mx0 = mn0 = 0.f; mx1 = mn1 = 0.f; }
    float* row = &g_s.cat[(size_t)node * 384];
    const float* hrow = &g_s.h[(size_t)node * 64];
    row[lane] = hrow[lane];
    row[lane + 32] = hrow[lane + 32];
    row[64 + lane] = s0;     row[96 + lane] = s1;
    row[128 + lane] = mean0; row[160 + lane] = mean1;
    row[192 + lane] = mx0;   row[224 + lane] = mx1;
    row[256 + lane] = mn0;   row[288 + lane] = mn1;
    row[320 + lane] = std0;  row[352 + lane] = std1;
}

// ---------------------------------------------------------------------------
// Fused GCN aggregation + head MLP: warp per node.
// ---------------------------------------------------------------------------
__global__ void gcn_head_kernel(const float* __restrict__ x,
                                const float* __restrict__ bg,
                                const float* __restrict__ Wh1, const float* __restrict__ bh1,
                                const float* __restrict__ Wh2, const float* __restrict__ bh2,
                                float* __restrict__ out)
{
    __shared__ float sW1[320], sW2[100], sb1[16], sb2[16], sbg[16];
    int t = threadIdx.x;
    for (int i = t; i < 320; i += blockDim.x) sW1[i] = Wh1[i];
    for (int i = t; i < 100; i += blockDim.x) sW2[i] = Wh2[i];
    if (t < 10) { sb1[t] = bh1[t]; sb2[t] = bh2[t]; }
    if (t < 16) sbg[t] = bg[t];
    __syncthreads();
    int node = (blockIdx.x * blockDim.x + t) >> 5;
    if (node >= NN) return;
    int lane = t & 31;
    int f = lane & 15, half = lane >> 4;
    int start = g_s.off[node], end = g_s.off[node + 1];
    float accA = 0.f, accB = 0.f;
    int i = start + half;
    for (; i + 2 < end; i += 4) {
        int sn0 = __ldcs(&g_s.csr_src[i]);
        int sn1 = __ldcs(&g_s.csr_src[i + 2]);
        accA = fmaf(g_s.hg[(size_t)sn0 * 16 + f], g_s.dinv[sn0], accA);
        accB = fmaf(g_s.hg[(size_t)sn1 * 16 + f], g_s.dinv[sn1], accB);
    }
    if (i < end) {
        int sn = __ldcs(&g_s.csr_src[i]);
        accA = fmaf(g_s.hg[(size_t)sn * 16 + f], g_s.dinv[sn], accA);
    }
    float acc = accA + accB;
    acc += __shfl_xor_sync(0xffffffffu, acc, 16);
    float dv = g_s.dinv[node];
    float self = g_s.hg[(size_t)node * 16 + f];
    float gval = fmaf(dv * dv, self, dv * acc) + sbg[f];
    float myv = (lane < 16) ? gval : x[(size_t)node * 16 + f];
    int col = (lane < 10) ? lane : 0;
    float z = sb1[col];
#pragma unroll
    for (int j = 0; j < 32; j++) {
        float v = __shfl_sync(0xffffffffu, myv, j);
        z = fmaf(v, sW1[j * 10 + col], z);
    }
    z = fmaxf(z, 0.f);
    float o = sb2[col];
#pragma unroll
    for (int j = 0; j < 10; j++) {
        float v = __shfl_sync(0xffffffffu, z, j);
        o = fmaf(v, sW2[j * 10 + col], o);
    }
    if (lane < 10) out[(size_t)node * 10 + lane] = o;
}

// ---------------------------------------------------------------------------
// Launch
// ---------------------------------------------------------------------------
extern "C" void kernel_launch(void* const* d_in, const int* in_sizes, int n_in,
                              void* d_out, int out_size)
{
    (void)in_sizes; (void)n_in; (void)out_size;
    const float* x      = (const float*)d_in[0];
    const int*   ei     = (const int*)d_in[1];
    const float* ea     = (const float*)d_in[2];
    const float* We0    = (const float*)d_in[3];
    const float* be0    = (const float*)d_in[4];
    const float* Wpre0  = (const float*)d_in[5];
    const float* bpre0  = (const float*)d_in[6];
    const float* Wpost0 = (const float*)d_in[7];
    const float* bpost0 = (const float*)d_in[8];
    const float* Wlin0  = (const float*)d_in[9];
    const float* blin0  = (const float*)d_in[10];
    const float* We1    = (const float*)d_in[11];
    const float* be1    = (const float*)d_in[12];
    const float* Wpre1  = (const float*)d_in[13];
    const float* bpre1  = (const float*)d_in[14];
    const float* Wpost1 = (const float*)d_in[15];
    const float* bpost1 = (const float*)d_in[16];
    const float* Wlin1  = (const float*)d_in[17];
    const float* blin1  = (const float*)d_in[18];
    const float* Wg     = (const float*)d_in[19];
    const float* bg     = (const float*)d_in[20];
    const float* Wh1    = (const float*)d_in[21];
    const float* bh1    = (const float*)d_in[22];
    const float* Wh2    = (const float*)d_in[23];
    const float* bh2    = (const float*)d_in[24];
    float* out = (float*)d_out;

    const int* src = ei;
    const int* dst = ei + EE;

    const int NB_SCAN = (NN + 2047) / 2048; // 49
    const int FOLD_WORK = 24576 + 6144 + 8192 + 512 + 256 + 64 + 64 + 16 + 64 + 64;

    // weight folding + cnt zeroing
    fold_zero_kernel<<<(NN + FOLD_WORK + 255) / 256, 256>>>(
        We0, be0, Wpre0, bpre0, Wpost0, bpost0, Wlin0, blin0,
        We1, be1, Wpre1, bpre1, Wpost1, bpost1, Wlin1, blin1);

    // CSR build (shared by both PNA layers and GCN)
    hist_kernel<<<(EE + 255) / 256, 256>>>(dst);
    scan1_kernel<<<NB_SCAN, 512>>>();
    scan3_kernel<<<(NN + 255) / 256, 256>>>();
    scatter_kernel<<<(EE + 255) / 256, 256>>>(src, dst, ea);

    // ---- PNA layer 0 ----
    mm_kernel<16, 32, 128, 16, 8, 8, false, false, 0><<<(NN + 127) / 128, 64>>>(x, nullptr);
    agg0_kernel<<<(NN * 32 + 255) / 256, 256>>>(x);
    mm_kernel<96, 64, 128, 32, 8, 8, true, true, 1><<<(NN + 127) / 128, 128>>>(nullptr, nullptr);

    // ---- PNA layer 1 ----
    mm_kernel<64, 128, 128, 32, 8, 8, false, false, 2><<<(NN + 127) / 128, 256>>>(nullptr, nullptr);
    agg1_kernel<<<(NN * 32 + 255) / 256, 256>>>();
    mm_kernel<384, 64, 128, 32, 8, 8, true, true, 3><<<(NN + 127) / 128, 128>>>(nullptr, nullptr);

    // ---- GCN matmul ----
    mm_kernel<64, 16, 128, 32, 4, 4, false, false, 4><<<(NN + 127) / 128, 128>>>(nullptr, Wg);

    // ---- fused GCN aggregation + head ----
    gcn_head_kernel<<<(NN * 32 + 255) / 256, 256>>>(x, bg, Wh1, bh1, Wh2, bh2, out);
}